// round 1
// baseline (speedup 1.0000x reference)
#include <cuda_runtime.h>
#include <cuda_bf16.h>

// out[b,c,t,l] = (x[b,c,i0,l] + x[b,c,i1,l] + x[b,c,i2,l]) / 3
// x: (32, 2, 24, 32768) fp32, out: (32, 2, 30, 32768) fp32 (reshape to 6x5 is a view)

#define NV 24
#define NT 30
#define L  32768
#define L4 (L / 4)   // 8192 float4 lanes per row

__global__ __launch_bounds__(256)
void tri_mean_kernel(const float4* __restrict__ x, float4* __restrict__ out) {
    const int l4 = blockIdx.x * blockDim.x + threadIdx.x;  // 0 .. L4-1
    const int bc = blockIdx.y;                             // 0 .. 63

    const float4* __restrict__ xb = x + (size_t)bc * NV * L4 + l4;
    float4* __restrict__ ob       = out + (size_t)bc * NT * L4 + l4;

    // Front-batched loads: 24 independent LDG.128 -> high MLP
    float4 v[NV];
#pragma unroll
    for (int i = 0; i < NV; i++) {
        v[i] = xb[(size_t)i * L4];
    }

    const float s = 1.0f / 3.0f;

    // Triangle table as compile-time constants (fully unrolled -> constant indices)
    const int t0[NT] = {0,0,1,1,2,3,4,4,5,5,7,7,8,8,9,10,11,11,12,12,14,14,15,15,16,17,18,18,19,19};
    const int t1[NT] = {3,1,4,2,5,4,7,5,8,6,10,8,11,9,12,11,14,12,15,13,17,15,18,16,19,18,21,19,22,20};
    const int t2[NT] = {4,4,5,5,6,7,8,8,9,9,11,11,12,12,13,14,15,15,16,16,18,18,19,19,20,21,22,22,23,23};

#pragma unroll
    for (int t = 0; t < NT; t++) {
        const float4 a = v[t0[t]];
        const float4 b = v[t1[t]];
        const float4 c = v[t2[t]];
        float4 r;
        r.x = (a.x + b.x + c.x) * s;
        r.y = (a.y + b.y + c.y) * s;
        r.z = (a.z + b.z + c.z) * s;
        r.w = (a.w + b.w + c.w) * s;
        ob[(size_t)t * L4] = r;
    }
}

extern "C" void kernel_launch(void* const* d_in, const int* in_sizes, int n_in,
                              void* d_out, int out_size) {
    const float4* x = (const float4*)d_in[0];
    float4* out = (float4*)d_out;

    dim3 block(256);
    dim3 grid(L4 / 256, 64);  // (32, 64)
    tri_mean_kernel<<<grid, block>>>(x, out);
}